// round 1
// baseline (speedup 1.0000x reference)
#include <cuda_runtime.h>

#define BATCH 4
#define SEQ   4096
#define EMBED 1024
#define HEAD  64
#define ROWS  (BATCH * SEQ)

// Scratch for projected q, k, v : [B*N, 64] each (4 MB each; device globals are the
// allowed scratch mechanism under the harness allocation guards).
__device__ float g_q[ROWS * HEAD];
__device__ float g_k[ROWS * HEAD];
__device__ float g_v[ROWS * HEAD];

// ---------------------------------------------------------------------------
// Projection: out[row, h] = sum_e x[row, e] * W[h, e]   (W row-major [64,1024])
// Block: 128 rows x 64 cols, 256 threads, thread micro-tile 8x4.
// grid = (ROWS/128, 3); grid.y selects Wq/Wk/Wv -> g_q/g_k/g_v.
// ---------------------------------------------------------------------------
__global__ void __launch_bounds__(256) proj_kernel(const float* __restrict__ x,
                                                   const float* __restrict__ Wq,
                                                   const float* __restrict__ Wk,
                                                   const float* __restrict__ Wv) {
    __shared__ float Xs[32][129];   // Xs[k][m], padded (scalar reads, conflict-free fills)
    __shared__ float Ws[32][64];    // Ws[k][n], float4-aligned rows

    const int t  = threadIdx.x;
    const int m_sel = blockIdx.y;
    const float* W    = (m_sel == 0) ? Wq : (m_sel == 1) ? Wk : Wv;
    float*       outp = (m_sel == 0) ? g_q : (m_sel == 1) ? g_k : g_v;

    const size_t row0 = (size_t)blockIdx.x * 128;
    const int tx = t & 15;   // col group: cols tx*4 .. tx*4+3
    const int ty = t >> 4;   // row group: rows ty*8 .. ty*8+7

    float acc[8][4];
#pragma unroll
    for (int i = 0; i < 8; i++)
#pragma unroll
        for (int j = 0; j < 4; j++) acc[i][j] = 0.f;

    for (int k0 = 0; k0 < EMBED; k0 += 32) {
        // Fill Xs (transposed): 128 rows x 32 k = 1024 float4 loads
#pragma unroll
        for (int j = 0; j < 4; j++) {
            int id = t + 256 * j;          // 0..1023
            int m  = id >> 3;              // row in tile
            int kq = id & 7;               // float4 index along k
            float4 v = *(const float4*)(x + (row0 + m) * EMBED + k0 + kq * 4);
            Xs[kq * 4 + 0][m] = v.x;
            Xs[kq * 4 + 1][m] = v.y;
            Xs[kq * 4 + 2][m] = v.z;
            Xs[kq * 4 + 3][m] = v.w;
        }
        // Fill Ws (transposed): 64 cols x 32 k = 512 float4 loads
#pragma unroll
        for (int j = 0; j < 2; j++) {
            int id = t + 256 * j;          // 0..511
            int nn = id >> 3;              // col
            int kq = id & 7;
            float4 v = *(const float4*)(W + (size_t)nn * EMBED + k0 + kq * 4);
            Ws[kq * 4 + 0][nn] = v.x;
            Ws[kq * 4 + 1][nn] = v.y;
            Ws[kq * 4 + 2][nn] = v.z;
            Ws[kq * 4 + 3][nn] = v.w;
        }
        __syncthreads();

#pragma unroll
        for (int k = 0; k < 32; k++) {
            float4 wv = *(const float4*)&Ws[k][tx * 4];
#pragma unroll
            for (int i = 0; i < 8; i++) {
                float xv = Xs[k][ty * 8 + i];
                acc[i][0] += xv * wv.x;
                acc[i][1] += xv * wv.y;
                acc[i][2] += xv * wv.z;
                acc[i][3] += xv * wv.w;
            }
        }
        __syncthreads();
    }

#pragma unroll
    for (int i = 0; i < 8; i++) {
        float4 r = make_float4(acc[i][0], acc[i][1], acc[i][2], acc[i][3]);
        *(float4*)(outp + (row0 + ty * 8 + i) * HEAD + tx * 4) = r;
    }
}

// ---------------------------------------------------------------------------
// Flash attention, fp32. BQ = BK = 64, 256 threads, grid = (SEQ/64, BATCH).
// Thread (tx = t&15, ty = t>>4):
//   S phase : rows r_i = ty + 16i (i<4), cols c_j = tx + 16j (j<4)  -> s[4][4]
//   PV phase: same rows, out cols h = 4*tx .. 4*tx+3                -> o4[4]
// Row softmax state (m, l, corr) stays in-register because row ownership is
// identical across phases. P is staged transposed in smem for the PV GEMM.
// ---------------------------------------------------------------------------
#define SM_QS   0               // Qs[64][64]
#define SM_KS   4096            // Ks[64][68]
#define SM_VS   8448            // Vs[64][68]
#define SM_PT   12800           // Pt[64][65]  (Pt[c][r])
#define SM_MSK  16960           // msk[64]
#define ATTN_SMEM_FLOATS 17024
#define ATTN_SMEM_BYTES  (ATTN_SMEM_FLOATS * 4)

__global__ void __launch_bounds__(256) attn_kernel(const int* __restrict__ mask,
                                                   float* __restrict__ out) {
    extern __shared__ float sm[];
    float* Qs  = sm + SM_QS;
    float* Ks  = sm + SM_KS;
    float* Vs  = sm + SM_VS;
    float* Pt  = sm + SM_PT;
    float* msk = sm + SM_MSK;

    const int t  = threadIdx.x;
    const int tx = t & 15;
    const int ty = t >> 4;
    const int b  = blockIdx.y;
    const int q0 = blockIdx.x * 64;

    const float* qbase = g_q + ((size_t)b * SEQ + q0) * HEAD;
    const float* kbase = g_k + (size_t)b * SEQ * HEAD;
    const float* vbase = g_v + (size_t)b * SEQ * HEAD;

    // Load Q tile (64 x 64 floats = 1024 float4)
#pragma unroll
    for (int j = 0; j < 4; j++) {
        int id = t + 256 * j;
        int r  = id >> 4;
        int hq = id & 15;
        ((float4*)Qs)[r * 16 + hq] = ((const float4*)qbase)[r * 16 + hq];
    }

    float  m_run[4], l_run[4];
    float4 o4[4];
#pragma unroll
    for (int i = 0; i < 4; i++) {
        m_run[i] = -1e30f;
        l_run[i] = 0.f;
        o4[i]    = make_float4(0.f, 0.f, 0.f, 0.f);
    }

    for (int kt = 0; kt < SEQ; kt += 64) {
        __syncthreads();   // previous tile's consumers (incl. Q load on iter 0) done
        // Load K/V tiles (each 64 keys x 64 h): rows padded to 68 floats
#pragma unroll
        for (int j = 0; j < 4; j++) {
            int id = t + 256 * j;
            int c  = id >> 4;
            int hq = id & 15;
            const float4* kp = (const float4*)(kbase + (size_t)(kt + c) * HEAD);
            const float4* vp = (const float4*)(vbase + (size_t)(kt + c) * HEAD);
            ((float4*)(Ks + c * 68))[hq] = kp[hq];
            ((float4*)(Vs + c * 68))[hq] = vp[hq];
        }
        if (t < 64) msk[t] = (mask[b * SEQ + kt + t] == 0) ? -1e30f : 0.f;
        __syncthreads();

        // ---- S = Q K^T (tile) ----
        float s[4][4];
#pragma unroll
        for (int i = 0; i < 4; i++)
#pragma unroll
            for (int j = 0; j < 4; j++) s[i][j] = 0.f;

#pragma unroll
        for (int hq = 0; hq < 16; hq++) {
            float4 q[4], k[4];
#pragma unroll
            for (int i = 0; i < 4; i++)
                q[i] = ((const float4*)(Qs + (ty + 16 * i) * 64))[hq];
#pragma unroll
            for (int j = 0; j < 4; j++)
                k[j] = ((const float4*)(Ks + (tx + 16 * j) * 68))[hq];
#pragma unroll
            for (int i = 0; i < 4; i++)
#pragma unroll
                for (int j = 0; j < 4; j++) {
                    s[i][j] += q[i].x * k[j].x;
                    s[i][j] += q[i].y * k[j].y;
                    s[i][j] += q[i].z * k[j].z;
                    s[i][j] += q[i].w * k[j].w;
                }
        }

        // ---- online softmax per row (rows ty+16i; reduce over the 16 tx lanes) ----
        float corr[4];
#pragma unroll
        for (int i = 0; i < 4; i++) {
            float v0 = s[i][0] * 0.125f + msk[tx];
            float v1 = s[i][1] * 0.125f + msk[tx + 16];
            float v2 = s[i][2] * 0.125f + msk[tx + 32];
            float v3 = s[i][3] * 0.125f + msk[tx + 48];
            float mx = fmaxf(fmaxf(v0, v1), fmaxf(v2, v3));
#pragma unroll
            for (int d = 1; d < 16; d <<= 1)
                mx = fmaxf(mx, __shfl_xor_sync(0xffffffffu, mx, d));
            float mnew = fmaxf(m_run[i], mx);
            float cr   = __expf(m_run[i] - mnew);
            m_run[i]   = mnew;
            corr[i]    = cr;
            float p0 = __expf(v0 - mnew);
            float p1 = __expf(v1 - mnew);
            float p2 = __expf(v2 - mnew);
            float p3 = __expf(v3 - mnew);
            float ls = (p0 + p1) + (p2 + p3);
#pragma unroll
            for (int d = 1; d < 16; d <<= 1)
                ls += __shfl_xor_sync(0xffffffffu, ls, d);
            l_run[i] = l_run[i] * cr + ls;
            Pt[(tx     ) * 65 + ty + 16 * i] = p0;
            Pt[(tx + 16) * 65 + ty + 16 * i] = p1;
            Pt[(tx + 32) * 65 + ty + 16 * i] = p2;
            Pt[(tx + 48) * 65 + ty + 16 * i] = p3;
        }
        __syncthreads();

        // ---- O = O*corr + P V (tile) ----
#pragma unroll
        for (int i = 0; i < 4; i++) {
            o4[i].x *= corr[i];
            o4[i].y *= corr[i];
            o4[i].z *= corr[i];
            o4[i].w *= corr[i];
        }
#pragma unroll 8
        for (int c = 0; c < 64; c++) {
            float4 v = ((const float4*)(Vs + c * 68))[tx];
#pragma unroll
            for (int i = 0; i < 4; i++) {
                float p = Pt[c * 65 + ty + 16 * i];
                o4[i].x += p * v.x;
                o4[i].y += p * v.y;
                o4[i].z += p * v.z;
                o4[i].w += p * v.w;
            }
        }
    }

    // ---- epilogue: divide by l, store ----
#pragma unroll
    for (int i = 0; i < 4; i++) {
        float inv = 1.f / l_run[i];
        float4 r  = o4[i];
        r.x *= inv; r.y *= inv; r.z *= inv; r.w *= inv;
        ((float4*)(out + ((size_t)b * SEQ + q0 + ty + 16 * i) * HEAD))[tx] = r;
    }
}

// ---------------------------------------------------------------------------
extern "C" void kernel_launch(void* const* d_in, const int* in_sizes, int n_in,
                              void* d_out, int out_size) {
    const float* x    = (const float*)d_in[0];
    const float* Wq   = (const float*)d_in[1];
    const float* Wk   = (const float*)d_in[2];
    const float* Wv   = (const float*)d_in[3];
    const int*   mask = (const int*)d_in[4];
    float*       out  = (float*)d_out;

    // 68 KB dynamic smem (>48 KB needs explicit opt-in; immediate API, capture-safe)
    cudaFuncSetAttribute(attn_kernel, cudaFuncAttributeMaxDynamicSharedMemorySize,
                         ATTN_SMEM_BYTES);

    proj_kernel<<<dim3(ROWS / 128, 3), 256>>>(x, Wq, Wk, Wv);
    attn_kernel<<<dim3(SEQ / 64, BATCH), 256, ATTN_SMEM_BYTES>>>(mask, out);
}

// round 2
// speedup vs baseline: 3.3602x; 3.3602x over previous
#include <cuda_runtime.h>
#include <cstdint>

#define BATCH 4
#define SEQ   4096
#define EMBED 1024
#define HEAD  64
#define ROWS  (BATCH * SEQ)

// Scratch: projected q, k (row-major [B*N, 64]) and v TRANSPOSED ([B, 64, N])
__device__ float g_q [ROWS * HEAD];
__device__ float g_k [ROWS * HEAD];
__device__ float g_vt[BATCH * HEAD * SEQ];

// ---------------------------------------------------------------------------
// helpers
// ---------------------------------------------------------------------------
__device__ __forceinline__ unsigned f2tf(float f) {
    unsigned u;
    asm("cvt.rna.tf32.f32 %0, %1;" : "=r"(u) : "f"(f));
    return u;
}

// D += A * B  (m16n8k8, tf32 in, f32 accumulate)
__device__ __forceinline__ void mma8(float* d, unsigned a0, unsigned a1,
                                     unsigned a2, unsigned a3,
                                     unsigned b0, unsigned b1) {
    asm("mma.sync.aligned.m16n8k8.row.col.f32.tf32.tf32.f32 "
        "{%0,%1,%2,%3},{%4,%5,%6,%7},{%8,%9},{%0,%1,%2,%3};"
        : "+f"(d[0]), "+f"(d[1]), "+f"(d[2]), "+f"(d[3])
        : "r"(a0), "r"(a1), "r"(a2), "r"(a3), "r"(b0), "r"(b1));
}

__device__ __forceinline__ void cp16(uint32_t saddr, const void* gaddr) {
    asm volatile("cp.async.ca.shared.global [%0], [%1], 16;" ::"r"(saddr), "l"(gaddr));
}

// ===========================================================================
// Projection (tf32 mma): out[row, n] = sum_e x[row, e] * W[n, e], n in [0,192)
// n<64 -> g_q, n<128 -> g_k, else -> g_vt (stored transposed [b][h][seq]).
// Block: 128 rows x 192 cols, 256 threads (8 warps: warp_m = wid&1 (64 rows),
// warp_n = wid>>1 (48 cols)). K-chunks of 32, cp.async double buffered.
// ===========================================================================
#define PKC   32
#define PSTR  40                       // 40 % 32 == 8 -> conflict-free frag LDS
#define XS_F  (128 * PSTR)             // 5120 floats
#define WS_F  (192 * PSTR)             // 7680 floats
#define PROJ_SMEM_F (2 * (XS_F + WS_F))
#define PROJ_SMEM_B (PROJ_SMEM_F * 4)  // 102400 B

__global__ void __launch_bounds__(256, 1)
proj_kernel(const float* __restrict__ x,  const float* __restrict__ Wq,
            const float* __restrict__ Wk, const float* __restrict__ Wv) {
    extern __shared__ float sm[];
    const int t = threadIdx.x, lane = t & 31, wid = t >> 5;
    const int g = lane >> 2, tq = lane & 3;
    const int wm = wid & 1, wn = wid >> 1;
    const size_t row0 = (size_t)blockIdx.x * 128;

    float acc[4][6][4];
#pragma unroll
    for (int mt = 0; mt < 4; mt++)
#pragma unroll
        for (int nt = 0; nt < 6; nt++)
#pragma unroll
            for (int i = 0; i < 4; i++) acc[mt][nt][i] = 0.f;

    const int NC = EMBED / PKC;  // 32 chunks

    // ---- issue cp.async loads for chunk c into buffer (c & 1) ----
    auto issue = [&](int c) {
        int buf = c & 1;
        int k0  = c * PKC;
        float* Xs = sm + buf * (XS_F + WS_F);
        float* Ws = Xs + XS_F;
#pragma unroll
        for (int j = 0; j < 4; j++) {            // X: 128 x 32 = 1024 float4
            int id = t + 256 * j;
            int r = id >> 3, q = id & 7;
            cp16((uint32_t)__cvta_generic_to_shared(&Xs[r * PSTR + 4 * q]),
                 x + (row0 + r) * EMBED + k0 + 4 * q);
        }
#pragma unroll
        for (int j = 0; j < 6; j++) {            // W: 192 x 32 = 1536 float4
            int id = t + 256 * j;
            int n = id >> 3, q = id & 7;
            const float* wsel = (n < 64) ? Wq : (n < 128) ? Wk : Wv;
            cp16((uint32_t)__cvta_generic_to_shared(&Ws[n * PSTR + 4 * q]),
                 wsel + (size_t)(n & 63) * EMBED + k0 + 4 * q);
        }
        asm volatile("cp.async.commit_group;");
    };

    issue(0);
    for (int c = 0; c < NC; c++) {
        if (c + 1 < NC) {
            issue(c + 1);
            asm volatile("cp.async.wait_group 1;");
        } else {
            asm volatile("cp.async.wait_group 0;");
        }
        __syncthreads();
        const float* Xs = sm + (c & 1) * (XS_F + WS_F);
        const float* Ws = Xs + XS_F;
#pragma unroll
        for (int kk = 0; kk < 4; kk++) {
            unsigned a[4][4];
#pragma unroll
            for (int mt = 0; mt < 4; mt++) {
                int r = 64 * wm + 16 * mt + g;
                float2 lo = *(const float2*)&Xs[(r    ) * PSTR + 8 * kk + 2 * tq];
                float2 hi = *(const float2*)&Xs[(r + 8) * PSTR + 8 * kk + 2 * tq];
                a[mt][0] = f2tf(lo.x); a[mt][1] = f2tf(hi.x);
                a[mt][2] = f2tf(lo.y); a[mt][3] = f2tf(hi.y);
            }
#pragma unroll
            for (int nt = 0; nt < 6; nt++) {
                float2 bb = *(const float2*)&Ws[(48 * wn + 8 * nt + g) * PSTR + 8 * kk + 2 * tq];
                unsigned b0 = f2tf(bb.x), b1 = f2tf(bb.y);
#pragma unroll
                for (int mt = 0; mt < 4; mt++)
                    mma8(acc[mt][nt], a[mt][0], a[mt][1], a[mt][2], a[mt][3], b0, b1);
            }
        }
        __syncthreads();
    }

    // ---- epilogue: scatter to g_q / g_k / g_vt ----
#pragma unroll
    for (int mt = 0; mt < 4; mt++) {
#pragma unroll
        for (int nt = 0; nt < 6; nt++) {
            int c0 = 48 * wn + 8 * nt + 2 * tq;
            int msel = c0 >> 6;        // uniform per (wn, nt)
            int h    = c0 & 63;
            int r1 = (int)row0 + 64 * wm + 16 * mt + g;
            int r2 = r1 + 8;
            float* a = acc[mt][nt];
            if (msel == 0) {
                *(float2*)&g_q[(size_t)r1 * 64 + h] = make_float2(a[0], a[1]);
                *(float2*)&g_q[(size_t)r2 * 64 + h] = make_float2(a[2], a[3]);
            } else if (msel == 1) {
                *(float2*)&g_k[(size_t)r1 * 64 + h] = make_float2(a[0], a[1]);
                *(float2*)&g_k[(size_t)r2 * 64 + h] = make_float2(a[2], a[3]);
            } else {
                int b1 = r1 >> 12, n1 = r1 & 4095;
                int b2 = r2 >> 12, n2 = r2 & 4095;
                g_vt[((size_t)b1 * 64 + h    ) * SEQ + n1] = a[0];
                g_vt[((size_t)b1 * 64 + h + 1) * SEQ + n1] = a[1];
                g_vt[((size_t)b2 * 64 + h    ) * SEQ + n2] = a[2];
                g_vt[((size_t)b2 * 64 + h + 1) * SEQ + n2] = a[3];
            }
        }
    }
}

// ===========================================================================
// Flash attention, tf32 mma. BQ = BK = 64, 256 threads (8 warps, 4x2).
// Q fragments live in registers for the whole k-loop. k-index permutation
// (tig -> 2t, tig+4 -> 2t+1) makes every fragment load a conflict-free LDS.64
// with row stride 72. V arrives pre-transposed (g_vt).
// ===========================================================================
#define STR 72
#define S_KS   0
#define S_VT   (64 * STR)            // 4608
#define S_PS   (2 * 64 * STR)        // 9216  (also Q staging)
#define S_PMAX (3 * 64 * STR)        // 13824 : [2][64]
#define S_PSUM (S_PMAX + 128)        // 13952 : [2][64]
#define S_MSK  (S_PSUM + 128)        // 14080 : [64]
#define ATTN_SMEM_F (S_MSK + 64)     // 14144
#define ATTN_SMEM_B (ATTN_SMEM_F * 4)

__global__ void __launch_bounds__(256, 2)
attn_kernel(const int* __restrict__ mask, float* __restrict__ out) {
    extern __shared__ float sm[];
    float* Ks   = sm + S_KS;
    float* Vt   = sm + S_VT;
    float* Ps   = sm + S_PS;
    float* pmax = sm + S_PMAX;
    float* psum = sm + S_PSUM;
    float* msk  = sm + S_MSK;

    const int t = threadIdx.x, lane = t & 31, wid = t >> 5;
    const int g = lane >> 2, tq = lane & 3;
    const int wm = wid & 3, wn = wid >> 2;
    const int r0 = wm * 16;      // warp's query rows
    const int cb = wn * 32;      // warp's key cols (S) / head cols (PV)
    const int b  = blockIdx.y;
    const int q0 = blockIdx.x * 64;

    const float* qbase = g_q + ((size_t)b * SEQ + q0) * HEAD;
    const float* kbase = g_k + (size_t)b * SEQ * HEAD;
    const float* vbase = g_vt + (size_t)b * HEAD * SEQ;

    // ---- stage Q through Ps (stride 72, tf32), load fragments to regs ----
#pragma unroll
    for (int j = 0; j < 4; j++) {
        int id = t + 256 * j;
        int r = id >> 4, q4 = id & 15;
        float4 v = *(const float4*)(qbase + (size_t)r * 64 + 4 * q4);
        uint4 u = make_uint4(f2tf(v.x), f2tf(v.y), f2tf(v.z), f2tf(v.w));
        *(uint4*)&Ps[r * STR + 4 * q4] = u;
    }
    __syncthreads();
    unsigned qa[8][4];
#pragma unroll
    for (int kk = 0; kk < 8; kk++) {
        uint2 lo = *(const uint2*)&Ps[(r0 + g    ) * STR + 8 * kk + 2 * tq];
        uint2 hi = *(const uint2*)&Ps[(r0 + g + 8) * STR + 8 * kk + 2 * tq];
        qa[kk][0] = lo.x; qa[kk][1] = hi.x; qa[kk][2] = lo.y; qa[kk][3] = hi.y;
    }

    float m_lo = -1e30f, m_hi = -1e30f, l_lo = 0.f, l_hi = 0.f;
    float o[4][4];
#pragma unroll
    for (int nt = 0; nt < 4; nt++)
#pragma unroll
        for (int i = 0; i < 4; i++) o[nt][i] = 0.f;

    // ---- prefetch tile 0 ----
    float4 kreg[4], vreg[4];
    float  mreg = 0.f;
#pragma unroll
    for (int j = 0; j < 4; j++) {
        int id = t + 256 * j;
        int r = id >> 4, q4 = id & 15;
        kreg[j] = *(const float4*)(kbase + (size_t)r * 64 + 4 * q4);
        vreg[j] = *(const float4*)(vbase + (size_t)r * SEQ + 4 * q4);
    }
    if (t < 64) mreg = (mask[b * SEQ + t] == 0) ? -1e30f : 0.f;

    for (int kt = 0; kt < SEQ; kt += 64) {
        __syncthreads();   // prev tile fully consumed
        // ---- stage K / Vt (tf32) + mask ----
#pragma unroll
        for (int j = 0; j < 4; j++) {
            int id = t + 256 * j;
            int r = id >> 4, q4 = id & 15;
            float4 kv = kreg[j], vv4 = vreg[j];
            *(uint4*)&Ks[r * STR + 4 * q4] =
                make_uint4(f2tf(kv.x), f2tf(kv.y), f2tf(kv.z), f2tf(kv.w));
            *(uint4*)&Vt[r * STR + 4 * q4] =
                make_uint4(f2tf(vv4.x), f2tf(vv4.y), f2tf(vv4.z), f2tf(vv4.w));
        }
        if (t < 64) msk[t] = mreg;
        __syncthreads();
        // ---- prefetch next tile ----
        if (kt + 64 < SEQ) {
#pragma unroll
            for (int j = 0; j < 4; j++) {
                int id = t + 256 * j;
                int r = id >> 4, q4 = id & 15;
                kreg[j] = *(const float4*)(kbase + (size_t)(kt + 64 + r) * 64 + 4 * q4);
                vreg[j] = *(const float4*)(vbase + (size_t)r * SEQ + kt + 64 + 4 * q4);
            }
            if (t < 64) mreg = (mask[b * SEQ + kt + 64 + t] == 0) ? -1e30f : 0.f;
        }

        // ---- S = Q K^T ----
        float s[4][4];
#pragma unroll
        for (int nt = 0; nt < 4; nt++)
#pragma unroll
            for (int i = 0; i < 4; i++) s[nt][i] = 0.f;
#pragma unroll
        for (int kk = 0; kk < 8; kk++) {
#pragma unroll
            for (int nt = 0; nt < 4; nt++) {
                uint2 bb = *(const uint2*)&Ks[(cb + 8 * nt + g) * STR + 8 * kk + 2 * tq];
                mma8(s[nt], qa[kk][0], qa[kk][1], qa[kk][2], qa[kk][3], bb.x, bb.y);
            }
        }

        // ---- online softmax ----
        const float SC = 0.125f;
        float vmx_lo = -1e30f, vmx_hi = -1e30f;
#pragma unroll
        for (int nt = 0; nt < 4; nt++) {
            float2 mk = *(const float2*)&msk[cb + 8 * nt + 2 * tq];
            s[nt][0] = s[nt][0] * SC + mk.x;
            s[nt][1] = s[nt][1] * SC + mk.y;
            s[nt][2] = s[nt][2] * SC + mk.x;
            s[nt][3] = s[nt][3] * SC + mk.y;
            vmx_lo = fmaxf(vmx_lo, fmaxf(s[nt][0], s[nt][1]));
            vmx_hi = fmaxf(vmx_hi, fmaxf(s[nt][2], s[nt][3]));
        }
        vmx_lo = fmaxf(vmx_lo, __shfl_xor_sync(0xffffffffu, vmx_lo, 1));
        vmx_lo = fmaxf(vmx_lo, __shfl_xor_sync(0xffffffffu, vmx_lo, 2));
        vmx_hi = fmaxf(vmx_hi, __shfl_xor_sync(0xffffffffu, vmx_hi, 1));
        vmx_hi = fmaxf(vmx_hi, __shfl_xor_sync(0xffffffffu, vmx_hi, 2));
        if (tq == 0) {
            pmax[wn * 64 + r0 + g]     = vmx_lo;
            pmax[wn * 64 + r0 + 8 + g] = vmx_hi;
        }
        __syncthreads();
        float Mlo = fmaxf(m_lo, fmaxf(pmax[r0 + g],     pmax[64 + r0 + g]));
        float Mhi = fmaxf(m_hi, fmaxf(pmax[r0 + 8 + g], pmax[64 + r0 + 8 + g]));
        float clo = __expf(m_lo - Mlo), chi = __expf(m_hi - Mhi);
        m_lo = Mlo; m_hi = Mhi;

        float slo = 0.f, shi = 0.f;
#pragma unroll
        for (int nt = 0; nt < 4; nt++) {
            float p0 = __expf(s[nt][0] - Mlo), p1 = __expf(s[nt][1] - Mlo);
            float p2 = __expf(s[nt][2] - Mhi), p3 = __expf(s[nt][3] - Mhi);
            slo += p0 + p1; shi += p2 + p3;
            *(uint2*)&Ps[(r0 + g    ) * STR + cb + 8 * nt + 2 * tq] =
                make_uint2(f2tf(p0), f2tf(p1));
            *(uint2*)&Ps[(r0 + g + 8) * STR + cb + 8 * nt + 2 * tq] =
                make_uint2(f2tf(p2), f2tf(p3));
        }
        slo += __shfl_xor_sync(0xffffffffu, slo, 1);
        slo += __shfl_xor_sync(0xffffffffu, slo, 2);
        shi += __shfl_xor_sync(0xffffffffu, shi, 1);
        shi += __shfl_xor_sync(0xffffffffu, shi, 2);
        if (tq == 0) {
            psum[wn * 64 + r0 + g]     = slo;
            psum[wn * 64 + r0 + 8 + g] = shi;
        }
        __syncthreads();
        l_lo = l_lo * clo + psum[r0 + g]     + psum[64 + r0 + g];
        l_hi = l_hi * chi + psum[r0 + 8 + g] + psum[64 + r0 + 8 + g];

        // ---- O = O*corr + P V ----
#pragma unroll
        for (int nt = 0; nt < 4; nt++) {
            o[nt][0] *= clo; o[nt][1] *= clo;
            o[nt][2] *= chi; o[nt][3] *= chi;
        }
#pragma unroll
        for (int kk = 0; kk < 8; kk++) {
            uint2 plo = *(const uint2*)&Ps[(r0 + g    ) * STR + 8 * kk + 2 * tq];
            uint2 phi = *(const uint2*)&Ps[(r0 + g + 8) * STR + 8 * kk + 2 * tq];
#pragma unroll
            for (int nt = 0; nt < 4; nt++) {
                uint2 bb = *(const uint2*)&Vt[(cb + 8 * nt + g) * STR + 8 * kk + 2 * tq];
                mma8(o[nt], plo.x, phi.x, plo.y, phi.y, bb.x, bb.y);
            }
        }
    }

    // ---- epilogue ----
    float ilo = 1.f / l_lo, ihi = 1.f / l_hi;
    size_t rlo = ((size_t)b * SEQ + q0 + r0 + g) * 64;
    size_t rhi = rlo + 8 * 64;
#pragma unroll
    for (int nt = 0; nt < 4; nt++) {
        int c0 = cb + 8 * nt + 2 * tq;
        *(float2*)&out[rlo + c0] = make_float2(o[nt][0] * ilo, o[nt][1] * ilo);
        *(float2*)&out[rhi + c0] = make_float2(o[nt][2] * ihi, o[nt][3] * ihi);
    }
}

// ---------------------------------------------------------------------------
extern "C" void kernel_launch(void* const* d_in, const int* in_sizes, int n_in,
                              void* d_out, int out_size) {
    const float* x    = (const float*)d_in[0];
    const float* Wq   = (const float*)d_in[1];
    const float* Wk   = (const float*)d_in[2];
    const float* Wv   = (const float*)d_in[3];
    const int*   mask = (const int*)d_in[4];
    float*       out  = (float*)d_out;

    cudaFuncSetAttribute(proj_kernel, cudaFuncAttributeMaxDynamicSharedMemorySize,
                         PROJ_SMEM_B);
    cudaFuncSetAttribute(attn_kernel, cudaFuncAttributeMaxDynamicSharedMemorySize,
                         ATTN_SMEM_B);

    proj_kernel<<<ROWS / 128, 256, PROJ_SMEM_B>>>(x, Wq, Wk, Wv);
    attn_kernel<<<dim3(SEQ / 64, BATCH), 256, ATTN_SMEM_B>>>(mask, out);
}

// round 3
// speedup vs baseline: 4.1408x; 1.2323x over previous
#include <cuda_runtime.h>
#include <cstdint>

#define BATCH 4
#define SEQ   4096
#define EMBED 1024
#define HEAD  64
#define ROWS  (BATCH * SEQ)
#define KSPLIT 2
#define KRANGE (SEQ / KSPLIT)     // 2048 keys per CTA
#define NT     (KRANGE / 64)      // 32 key tiles per CTA

// Scratch: projected q, k (row-major [B*N, 64]) and v transposed ([B, 64, N]),
// all pre-rounded to tf32. Split-K partials: unnormalized O and (m, l).
__device__ float g_q [ROWS * HEAD];
__device__ float g_k [ROWS * HEAD];
__device__ float g_vt[BATCH * HEAD * SEQ];
__device__ float g_opart[KSPLIT * ROWS * HEAD];
__device__ float g_ml  [KSPLIT * ROWS * 2];

// ---------------------------------------------------------------------------
__device__ __forceinline__ unsigned f2tf(float f) {
    unsigned u;
    asm("cvt.rna.tf32.f32 %0, %1;" : "=r"(u) : "f"(f));
    return u;
}
__device__ __forceinline__ float f2tff(float f) { return __uint_as_float(f2tf(f)); }

// D += A * B  (m16n8k8, tf32 in, f32 accumulate)
__device__ __forceinline__ void mma8(float* d, unsigned a0, unsigned a1,
                                     unsigned a2, unsigned a3,
                                     unsigned b0, unsigned b1) {
    asm("mma.sync.aligned.m16n8k8.row.col.f32.tf32.tf32.f32 "
        "{%0,%1,%2,%3},{%4,%5,%6,%7},{%8,%9},{%0,%1,%2,%3};"
        : "+f"(d[0]), "+f"(d[1]), "+f"(d[2]), "+f"(d[3])
        : "r"(a0), "r"(a1), "r"(a2), "r"(a3), "r"(b0), "r"(b1));
}

__device__ __forceinline__ void cp16(void* sptr, const void* gaddr) {
    uint32_t sa = (uint32_t)__cvta_generic_to_shared(sptr);
    asm volatile("cp.async.ca.shared.global [%0], [%1], 16;" ::"r"(sa), "l"(gaddr));
}
__device__ __forceinline__ void cp_commit() { asm volatile("cp.async.commit_group;"); }

// ===========================================================================
// Projection (tf32 mma): out[row, n] = sum_e x[row, e] * W[n, e], n in [0,192)
// n<64 -> g_q, n<128 -> g_k, else -> g_vt (stored transposed [b][h][seq]).
// Outputs are pre-rounded to tf32 so attention can cp.async them directly.
// ===========================================================================
#define PKC   32
#define PSTR  40
#define XS_F  (128 * PSTR)
#define WS_F  (192 * PSTR)
#define PROJ_SMEM_F (2 * (XS_F + WS_F))
#define PROJ_SMEM_B (PROJ_SMEM_F * 4)

__global__ void __launch_bounds__(256, 1)
proj_kernel(const float* __restrict__ x,  const float* __restrict__ Wq,
            const float* __restrict__ Wk, const float* __restrict__ Wv) {
    extern __shared__ float sm[];
    const int t = threadIdx.x, lane = t & 31, wid = t >> 5;
    const int g = lane >> 2, tq = lane & 3;
    const int wm = wid & 1, wn = wid >> 1;
    const size_t row0 = (size_t)blockIdx.x * 128;

    float acc[4][6][4];
#pragma unroll
    for (int mt = 0; mt < 4; mt++)
#pragma unroll
        for (int nt = 0; nt < 6; nt++)
#pragma unroll
            for (int i = 0; i < 4; i++) acc[mt][nt][i] = 0.f;

    const int NC = EMBED / PKC;

    auto issue = [&](int c) {
        int buf = c & 1;
        int k0  = c * PKC;
        float* Xs = sm + buf * (XS_F + WS_F);
        float* Ws = Xs + XS_F;
#pragma unroll
        for (int j = 0; j < 4; j++) {
            int id = t + 256 * j;
            int r = id >> 3, q = id & 7;
            cp16(&Xs[r * PSTR + 4 * q], x + (row0 + r) * EMBED + k0 + 4 * q);
        }
#pragma unroll
        for (int j = 0; j < 6; j++) {
            int id = t + 256 * j;
            int n = id >> 3, q = id & 7;
            const float* wsel = (n < 64) ? Wq : (n < 128) ? Wk : Wv;
            cp16(&Ws[n * PSTR + 4 * q], wsel + (size_t)(n & 63) * EMBED + k0 + 4 * q);
        }
        cp_commit();
    };

    issue(0);
    for (int c = 0; c < NC; c++) {
        if (c + 1 < NC) {
            issue(c + 1);
            asm volatile("cp.async.wait_group 1;");
        } else {
            asm volatile("cp.async.wait_group 0;");
        }
        __syncthreads();
        const float* Xs = sm + (c & 1) * (XS_F + WS_F);
        const float* Ws = Xs + XS_F;
#pragma unroll
        for (int kk = 0; kk < 4; kk++) {
            unsigned a[4][4];
#pragma unroll
            for (int mt = 0; mt < 4; mt++) {
                int r = 64 * wm + 16 * mt + g;
                float2 lo = *(const float2*)&Xs[(r    ) * PSTR + 8 * kk + 2 * tq];
                float2 hi = *(const float2*)&Xs[(r + 8) * PSTR + 8 * kk + 2 * tq];
                a[mt][0] = f2tf(lo.x); a[mt][1] = f2tf(hi.x);
                a[mt][2] = f2tf(lo.y); a[mt][3] = f2tf(hi.y);
            }
#pragma unroll
            for (int nt = 0; nt < 6; nt++) {
                float2 bb = *(const float2*)&Ws[(48 * wn + 8 * nt + g) * PSTR + 8 * kk + 2 * tq];
                unsigned b0 = f2tf(bb.x), b1 = f2tf(bb.y);
#pragma unroll
                for (int mt = 0; mt < 4; mt++)
                    mma8(acc[mt][nt], a[mt][0], a[mt][1], a[mt][2], a[mt][3], b0, b1);
            }
        }
        __syncthreads();
    }

#pragma unroll
    for (int mt = 0; mt < 4; mt++) {
#pragma unroll
        for (int nt = 0; nt < 6; nt++) {
            int c0 = 48 * wn + 8 * nt + 2 * tq;
            int msel = c0 >> 6;
            int h    = c0 & 63;
            int r1 = (int)row0 + 64 * wm + 16 * mt + g;
            int r2 = r1 + 8;
            float* a = acc[mt][nt];
            float a0 = f2tff(a[0]), a1 = f2tff(a[1]);
            float a2 = f2tff(a[2]), a3 = f2tff(a[3]);
            if (msel == 0) {
                *(float2*)&g_q[(size_t)r1 * 64 + h] = make_float2(a0, a1);
                *(float2*)&g_q[(size_t)r2 * 64 + h] = make_float2(a2, a3);
            } else if (msel == 1) {
                *(float2*)&g_k[(size_t)r1 * 64 + h] = make_float2(a0, a1);
                *(float2*)&g_k[(size_t)r2 * 64 + h] = make_float2(a2, a3);
            } else {
                int b1 = r1 >> 12, n1 = r1 & 4095;
                int b2 = r2 >> 12, n2 = r2 & 4095;
                g_vt[((size_t)b1 * 64 + h    ) * SEQ + n1] = a0;
                g_vt[((size_t)b1 * 64 + h + 1) * SEQ + n1] = a1;
                g_vt[((size_t)b2 * 64 + h    ) * SEQ + n2] = a2;
                g_vt[((size_t)b2 * 64 + h + 1) * SEQ + n2] = a3;
            }
        }
    }
}

// ===========================================================================
// Flash attention, tf32 mma. BQ = 128, BK = 64, 256 threads (8 warps, each
// owning 16 full rows x 64 cols). Warp-local softmax; P stays in registers
// (accumulator layout == A-fragment layout under the k-permutation trick).
// K/V/Q pre-rounded tf32 -> cp.async double-buffered staging. Split-K x2.
// ===========================================================================
#define STR 72
#define S_Q  0                       // 128 x 72
#define S_K  9216                    // 2 x 64 x 72
#define S_V  18432                   // 2 x 64 x 72
#define S_M  27648                   // 2 x 64
#define ATTN_SMEM_F 27776
#define ATTN_SMEM_B (ATTN_SMEM_F * 4)   // 111104 B

__global__ void __launch_bounds__(256, 2)
attn_kernel(const int* __restrict__ mask) {
    extern __shared__ float sm[];
    float* Qs = sm + S_Q;
    float* Kb = sm + S_K;
    float* Vb = sm + S_V;
    float* Mb = sm + S_M;

    const int t = threadIdx.x, lane = t & 31;
    const int g = lane >> 2, tq = lane & 3;
    const int r0 = (t >> 5) * 16;     // warp's 16 query rows
    const int b  = blockIdx.y, z = blockIdx.z;
    const int q0 = blockIdx.x * 128;
    const int koff = z * KRANGE;

    const float* qbase = g_q + ((size_t)b * SEQ + q0) * HEAD;
    const float* kbase = g_k + ((size_t)b * SEQ + koff) * HEAD;
    const float* vbase = g_vt + (size_t)b * HEAD * SEQ + koff;

    // ---- stage Q (128 x 64) via cp.async ----
#pragma unroll
    for (int j = 0; j < 8; j++) {
        int id = t + 256 * j;
        int r = id >> 4, q = id & 15;
        cp16(&Qs[r * STR + 4 * q], qbase + (size_t)r * 64 + 4 * q);
    }
    cp_commit();

    auto issue = [&](int it) {
        int bf = it & 1;
        float* Ks = Kb + bf * (64 * STR);
        float* Vs = Vb + bf * (64 * STR);
#pragma unroll
        for (int j = 0; j < 4; j++) {
            int id = t + 256 * j;
            int r = id >> 4, q = id & 15;
            cp16(&Ks[r * STR + 4 * q], kbase + (size_t)(it * 64 + r) * 64 + 4 * q);
            cp16(&Vs[r * STR + 4 * q], vbase + (size_t)r * SEQ + it * 64 + 4 * q);
        }
        if (t < 64)
            Mb[bf * 64 + t] = (mask[b * SEQ + koff + it * 64 + t] == 0) ? -1e30f : 0.f;
        cp_commit();
    };

    float m_lo = -1e30f, m_hi = -1e30f, l_lo = 0.f, l_hi = 0.f;
    float o[8][4];
#pragma unroll
    for (int nt = 0; nt < 8; nt++)
#pragma unroll
        for (int i = 0; i < 4; i++) o[nt][i] = 0.f;

    issue(0);
    for (int it = 0; it < NT; it++) {
        if (it + 1 < NT) {
            issue(it + 1);
            asm volatile("cp.async.wait_group 1;");
        } else {
            asm volatile("cp.async.wait_group 0;");
        }
        __syncthreads();
        const int bf = it & 1;
        const float* Ks = Kb + bf * (64 * STR);
        const float* Vs = Vb + bf * (64 * STR);
        const float* mk = Mb + bf * 64;

        // ---- S = Q K^T : warp tile 16 x 64 ----
        float s[8][4];
#pragma unroll
        for (int nt = 0; nt < 8; nt++)
#pragma unroll
            for (int i = 0; i < 4; i++) s[nt][i] = 0.f;
#pragma unroll
        for (int kk = 0; kk < 8; kk++) {
            uint2 qlo = *(const uint2*)&Qs[(r0 + g    ) * STR + 8 * kk + 2 * tq];
            uint2 qhi = *(const uint2*)&Qs[(r0 + g + 8) * STR + 8 * kk + 2 * tq];
#pragma unroll
            for (int nt = 0; nt < 8; nt++) {
                uint2 bb = *(const uint2*)&Ks[(8 * nt + g) * STR + 8 * kk + 2 * tq];
                mma8(s[nt], qlo.x, qhi.x, qlo.y, qhi.y, bb.x, bb.y);
            }
        }

        // ---- warp-local online softmax (rows g, g+8) ----
        const float SC = 0.125f;
        float vmx_lo = -1e30f, vmx_hi = -1e30f;
#pragma unroll
        for (int nt = 0; nt < 8; nt++) {
            float2 mm = *(const float2*)&mk[8 * nt + 2 * tq];
            s[nt][0] = s[nt][0] * SC + mm.x;
            s[nt][1] = s[nt][1] * SC + mm.y;
            s[nt][2] = s[nt][2] * SC + mm.x;
            s[nt][3] = s[nt][3] * SC + mm.y;
            vmx_lo = fmaxf(vmx_lo, fmaxf(s[nt][0], s[nt][1]));
            vmx_hi = fmaxf(vmx_hi, fmaxf(s[nt][2], s[nt][3]));
        }
        vmx_lo = fmaxf(vmx_lo, __shfl_xor_sync(0xffffffffu, vmx_lo, 1));
        vmx_lo = fmaxf(vmx_lo, __shfl_xor_sync(0xffffffffu, vmx_lo, 2));
        vmx_hi = fmaxf(vmx_hi, __shfl_xor_sync(0xffffffffu, vmx_hi, 1));
        vmx_hi = fmaxf(vmx_hi, __shfl_xor_sync(0xffffffffu, vmx_hi, 2));
        float Mlo = fmaxf(m_lo, vmx_lo), Mhi = fmaxf(m_hi, vmx_hi);
        float clo = __expf(m_lo - Mlo), chi = __expf(m_hi - Mhi);
        m_lo = Mlo; m_hi = Mhi;

        float slo = 0.f, shi = 0.f;
#pragma unroll
        for (int nt = 0; nt < 8; nt++) {
            float p0 = __expf(s[nt][0] - Mlo), p1 = __expf(s[nt][1] - Mlo);
            float p2 = __expf(s[nt][2] - Mhi), p3 = __expf(s[nt][3] - Mhi);
            slo += p0 + p1; shi += p2 + p3;
            s[nt][0] = __uint_as_float(f2tf(p0));
            s[nt][1] = __uint_as_float(f2tf(p1));
            s[nt][2] = __uint_as_float(f2tf(p2));
            s[nt][3] = __uint_as_float(f2tf(p3));
        }
        slo += __shfl_xor_sync(0xffffffffu, slo, 1);
        slo += __shfl_xor_sync(0xffffffffu, slo, 2);
        shi += __shfl_xor_sync(0xffffffffu, shi, 1);
        shi += __shfl_xor_sync(0xffffffffu, shi, 2);
        l_lo = l_lo * clo + slo;
        l_hi = l_hi * chi + shi;

        // ---- O = O*corr + P V : P straight from registers ----
#pragma unroll
        for (int nt = 0; nt < 8; nt++) {
            o[nt][0] *= clo; o[nt][1] *= clo;
            o[nt][2] *= chi; o[nt][3] *= chi;
        }
#pragma unroll
        for (int kc = 0; kc < 8; kc++) {
            unsigned a0 = __float_as_uint(s[kc][0]);
            unsigned a1 = __float_as_uint(s[kc][2]);
            unsigned a2 = __float_as_uint(s[kc][1]);
            unsigned a3 = __float_as_uint(s[kc][3]);
#pragma unroll
            for (int nh = 0; nh < 8; nh++) {
                uint2 bb = *(const uint2*)&Vs[(8 * nh + g) * STR + 8 * kc + 2 * tq];
                mma8(o[nh], a0, a1, a2, a3, bb.x, bb.y);
            }
        }
        __syncthreads();
    }

    // ---- epilogue: unnormalized O + (m, l) to split-K scratch ----
    size_t rlo = (size_t)z * ROWS + (size_t)b * SEQ + q0 + r0 + g;
    size_t rhi = rlo + 8;
#pragma unroll
    for (int nt = 0; nt < 8; nt++) {
        int c0 = 8 * nt + 2 * tq;
        *(float2*)&g_opart[rlo * 64 + c0] = make_float2(o[nt][0], o[nt][1]);
        *(float2*)&g_opart[rhi * 64 + c0] = make_float2(o[nt][2], o[nt][3]);
    }
    if (tq == 0) {
        g_ml[rlo * 2] = m_lo; g_ml[rlo * 2 + 1] = l_lo;
        g_ml[rhi * 2] = m_hi; g_ml[rhi * 2 + 1] = l_hi;
    }
}

// ===========================================================================
// Split-K combine: out = (w0*O0 + w1*O1) / (w0*l0 + w1*l1)
// ===========================================================================
__global__ void __launch_bounds__(256) combine_kernel(float* __restrict__ out) {
    int t = threadIdx.x;
    int row = blockIdx.x * 16 + (t >> 4);
    int c   = (t & 15) * 4;
    float m0 = g_ml[(size_t)row * 2], l0 = g_ml[(size_t)row * 2 + 1];
    float m1 = g_ml[((size_t)ROWS + row) * 2], l1 = g_ml[((size_t)ROWS + row) * 2 + 1];
    float mx = fmaxf(m0, m1);
    float w0 = __expf(m0 - mx), w1 = __expf(m1 - mx);
    float inv = 1.f / (w0 * l0 + w1 * l1);
    w0 *= inv; w1 *= inv;
    float4 a = *(const float4*)&g_opart[(size_t)row * 64 + c];
    float4 d = *(const float4*)&g_opart[((size_t)ROWS + row) * 64 + c];
    float4 r = make_float4(w0 * a.x + w1 * d.x, w0 * a.y + w1 * d.y,
                           w0 * a.z + w1 * d.z, w0 * a.w + w1 * d.w);
    *(float4*)&out[(size_t)row * 64 + c] = r;
}

// ---------------------------------------------------------------------------
extern "C" void kernel_launch(void* const* d_in, const int* in_sizes, int n_in,
                              void* d_out, int out_size) {
    const float* x    = (const float*)d_in[0];
    const float* Wq   = (const float*)d_in[1];
    const float* Wk   = (const float*)d_in[2];
    const float* Wv   = (const float*)d_in[3];
    const int*   mask = (const int*)d_in[4];
    float*       out  = (float*)d_out;

    cudaFuncSetAttribute(proj_kernel, cudaFuncAttributeMaxDynamicSharedMemorySize,
                         PROJ_SMEM_B);
    cudaFuncSetAttribute(attn_kernel, cudaFuncAttributeMaxDynamicSharedMemorySize,
                         ATTN_SMEM_B);

    proj_kernel<<<ROWS / 128, 256, PROJ_SMEM_B>>>(x, Wq, Wk, Wv);
    attn_kernel<<<dim3(SEQ / 128, BATCH, KSPLIT), 256, ATTN_SMEM_B>>>(mask);
    combine_kernel<<<ROWS / 16, 256>>>(out);
}

// round 4
// speedup vs baseline: 4.2275x; 1.0209x over previous
#include <cuda_runtime.h>
#include <cstdint>

#define BATCH 4
#define SEQ   4096
#define EMBED 1024
#define HEAD  64
#define ROWS  (BATCH * SEQ)
#define KSPLIT 2
#define KRANGE (SEQ / KSPLIT)
#define NT     (KRANGE / 64)

#define LOG2E 1.4426950408889634f

// Scratch: pre-rounded tf32 weights, projected q/k (row-major) and v transposed.
__device__ float g_w [192 * EMBED];
__device__ float g_q [ROWS * HEAD];
__device__ float g_k [ROWS * HEAD];
__device__ float g_vt[BATCH * HEAD * SEQ];
__device__ float g_opart[KSPLIT * ROWS * HEAD];
__device__ float g_ml  [KSPLIT * ROWS * 2];

// ---------------------------------------------------------------------------
__device__ __forceinline__ unsigned f2tf(float f) {
    unsigned u;
    asm("cvt.rna.tf32.f32 %0, %1;" : "=r"(u) : "f"(f));
    return u;
}
__device__ __forceinline__ float f2tff(float f) { return __uint_as_float(f2tf(f)); }

__device__ __forceinline__ void mma8(float* d, unsigned a0, unsigned a1,
                                     unsigned a2, unsigned a3,
                                     unsigned b0, unsigned b1) {
    asm("mma.sync.aligned.m16n8k8.row.col.f32.tf32.tf32.f32 "
        "{%0,%1,%2,%3},{%4,%5,%6,%7},{%8,%9},{%0,%1,%2,%3};"
        : "+f"(d[0]), "+f"(d[1]), "+f"(d[2]), "+f"(d[3])
        : "r"(a0), "r"(a1), "r"(a2), "r"(a3), "r"(b0), "r"(b1));
}

__device__ __forceinline__ void cp16(void* sptr, const void* gaddr) {
    uint32_t sa = (uint32_t)__cvta_generic_to_shared(sptr);
    asm volatile("cp.async.ca.shared.global [%0], [%1], 16;" ::"r"(sa), "l"(gaddr));
}
__device__ __forceinline__ void cp_commit() { asm volatile("cp.async.commit_group;"); }

// ===========================================================================
// Weight pre-round: g_w[n][e] = tf32(W[n][e]), n in [0,192)
// ===========================================================================
__global__ void __launch_bounds__(256) wcvt_kernel(const float* __restrict__ Wq,
                                                   const float* __restrict__ Wk,
                                                   const float* __restrict__ Wv) {
    int idx4 = blockIdx.x * 256 + threadIdx.x;   // grid 192: one float4 each
    int n  = idx4 >> 8;
    int e4 = idx4 & 255;
    const float* src = (n < 64) ? Wq : (n < 128) ? Wk : Wv;
    float4 v = *(const float4*)(src + (size_t)(n & 63) * EMBED + 4 * e4);
    v.x = f2tff(v.x); v.y = f2tff(v.y); v.z = f2tff(v.z); v.w = f2tff(v.w);
    *(float4*)(g_w + (size_t)n * EMBED + 4 * e4) = v;
}

// ===========================================================================
// Projection (tf32 mma): tile 64 rows x 192 cols, 256 threads (8 warps:
// wm = wid&1 -> 32 rows, wn = wid>>1 -> 48 cols). W pre-rounded (raw loads);
// X rounded inline. Outputs tf32-rounded. grid = ROWS/64 = 256, 2 CTAs/SM.
// ===========================================================================
#define PKC   32
#define PSTR  40
#define XS_F  (64 * PSTR)              // 2560 floats
#define WS_F  (192 * PSTR)             // 7680 floats
#define PROJ_SMEM_F (2 * (XS_F + WS_F))
#define PROJ_SMEM_B (PROJ_SMEM_F * 4)  // 81920 B

__global__ void __launch_bounds__(256, 2)
proj_kernel(const float* __restrict__ x) {
    extern __shared__ float sm[];
    const int t = threadIdx.x, lane = t & 31, wid = t >> 5;
    const int g = lane >> 2, tq = lane & 3;
    const int wm = wid & 1, wn = wid >> 1;
    const size_t row0 = (size_t)blockIdx.x * 64;

    float acc[2][6][4];
#pragma unroll
    for (int mt = 0; mt < 2; mt++)
#pragma unroll
        for (int nt = 0; nt < 6; nt++)
#pragma unroll
            for (int i = 0; i < 4; i++) acc[mt][nt][i] = 0.f;

    const int NC = EMBED / PKC;

    auto issue = [&](int c) {
        int buf = c & 1;
        int k0  = c * PKC;
        float* Xs = sm + buf * (XS_F + WS_F);
        float* Ws = Xs + XS_F;
#pragma unroll
        for (int j = 0; j < 2; j++) {            // X: 64 x 32 = 512 float4
            int id = t + 256 * j;
            int r = id >> 3, q = id & 7;
            cp16(&Xs[r * PSTR + 4 * q], x + (row0 + r) * EMBED + k0 + 4 * q);
        }
#pragma unroll
        for (int j = 0; j < 6; j++) {            // W: 192 x 32 = 1536 float4
            int id = t + 256 * j;
            int n = id >> 3, q = id & 7;
            cp16(&Ws[n * PSTR + 4 * q], g_w + (size_t)n * EMBED + k0 + 4 * q);
        }
        cp_commit();
    };

    issue(0);
    for (int c = 0; c < NC; c++) {
        if (c + 1 < NC) {
            issue(c + 1);
            asm volatile("cp.async.wait_group 1;");
        } else {
            asm volatile("cp.async.wait_group 0;");
        }
        __syncthreads();
        const float* Xs = sm + (c & 1) * (XS_F + WS_F);
        const float* Ws = Xs + XS_F;
#pragma unroll
        for (int kk = 0; kk < 4; kk++) {
            unsigned a[2][4];
#pragma unroll
            for (int mt = 0; mt < 2; mt++) {
                int r = 32 * wm + 16 * mt + g;
                float2 lo = *(const float2*)&Xs[(r    ) * PSTR + 8 * kk + 2 * tq];
                float2 hi = *(const float2*)&Xs[(r + 8) * PSTR + 8 * kk + 2 * tq];
                a[mt][0] = f2tf(lo.x); a[mt][1] = f2tf(hi.x);
                a[mt][2] = f2tf(lo.y); a[mt][3] = f2tf(hi.y);
            }
#pragma unroll
            for (int nt = 0; nt < 6; nt++) {
                uint2 bb = *(const uint2*)&Ws[(48 * wn + 8 * nt + g) * PSTR + 8 * kk + 2 * tq];
#pragma unroll
                for (int mt = 0; mt < 2; mt++)
                    mma8(acc[mt][nt], a[mt][0], a[mt][1], a[mt][2], a[mt][3],
                         bb.x, bb.y);
            }
        }
        __syncthreads();
    }

#pragma unroll
    for (int mt = 0; mt < 2; mt++) {
#pragma unroll
        for (int nt = 0; nt < 6; nt++) {
            int c0 = 48 * wn + 8 * nt + 2 * tq;
            int msel = c0 >> 6;
            int h    = c0 & 63;
            int r1 = (int)row0 + 32 * wm + 16 * mt + g;
            int r2 = r1 + 8;
            float* a = acc[mt][nt];
            float a0 = f2tff(a[0]), a1 = f2tff(a[1]);
            float a2 = f2tff(a[2]), a3 = f2tff(a[3]);
            if (msel == 0) {
                *(float2*)&g_q[(size_t)r1 * 64 + h] = make_float2(a0, a1);
                *(float2*)&g_q[(size_t)r2 * 64 + h] = make_float2(a2, a3);
            } else if (msel == 1) {
                *(float2*)&g_k[(size_t)r1 * 64 + h] = make_float2(a0, a1);
                *(float2*)&g_k[(size_t)r2 * 64 + h] = make_float2(a2, a3);
            } else {
                int b1 = r1 >> 12, n1 = r1 & 4095;
                int b2 = r2 >> 12, n2 = r2 & 4095;
                g_vt[((size_t)b1 * 64 + h    ) * SEQ + n1] = a0;
                g_vt[((size_t)b1 * 64 + h + 1) * SEQ + n1] = a1;
                g_vt[((size_t)b2 * 64 + h    ) * SEQ + n2] = a2;
                g_vt[((size_t)b2 * 64 + h + 1) * SEQ + n2] = a3;
            }
        }
    }
}

// ===========================================================================
// Flash attention, tf32 mma. BQ = 128, BK = 64, 256 threads (8 warps x 16
// rows x 64 cols). Q fragments hoisted to registers for the whole loop;
// warp-local softmax in log2 domain (bare exp2f); P stays in registers.
// Split-K x2.
// ===========================================================================
#define STR 72
#define S_Q  0
#define S_K  9216
#define S_V  18432
#define S_M  27648
#define ATTN_SMEM_F 27776
#define ATTN_SMEM_B (ATTN_SMEM_F * 4)

__global__ void __launch_bounds__(256, 2)
attn_kernel(const int* __restrict__ mask) {
    extern __shared__ float sm[];
    float* Qs = sm + S_Q;
    float* Kb = sm + S_K;
    float* Vb = sm + S_V;
    float* Mb = sm + S_M;

    const int t = threadIdx.x, lane = t & 31;
    const int g = lane >> 2, tq = lane & 3;
    const int r0 = (t >> 5) * 16;
    const int b  = blockIdx.y, z = blockIdx.z;
    const int q0 = blockIdx.x * 128;
    const int koff = z * KRANGE;

    const float* qbase = g_q + ((size_t)b * SEQ + q0) * HEAD;
    const float* kbase = g_k + ((size_t)b * SEQ + koff) * HEAD;
    const float* vbase = g_vt + (size_t)b * HEAD * SEQ + koff;

    // ---- stage Q ----
#pragma unroll
    for (int j = 0; j < 8; j++) {
        int id = t + 256 * j;
        int r = id >> 4, q = id & 15;
        cp16(&Qs[r * STR + 4 * q], qbase + (size_t)r * 64 + 4 * q);
    }
    cp_commit();

    auto issue = [&](int it) {
        int bf = it & 1;
        float* Ks = Kb + bf * (64 * STR);
        float* Vs = Vb + bf * (64 * STR);
#pragma unroll
        for (int j = 0; j < 4; j++) {
            int id = t + 256 * j;
            int r = id >> 4, q = id & 15;
            cp16(&Ks[r * STR + 4 * q], kbase + (size_t)(it * 64 + r) * 64 + 4 * q);
            cp16(&Vs[r * STR + 4 * q], vbase + (size_t)r * SEQ + it * 64 + 4 * q);
        }
        if (t < 64)
            Mb[bf * 64 + t] = (mask[b * SEQ + koff + it * 64 + t] == 0) ? -1e30f : 0.f;
        cp_commit();
    };

    issue(0);
    asm volatile("cp.async.wait_group 1;");   // Q group done
    __syncthreads();

    // ---- hoist Q fragments to registers ----
    unsigned qa[8][4];
#pragma unroll
    for (int kk = 0; kk < 8; kk++) {
        uint2 lo = *(const uint2*)&Qs[(r0 + g    ) * STR + 8 * kk + 2 * tq];
        uint2 hi = *(const uint2*)&Qs[(r0 + g + 8) * STR + 8 * kk + 2 * tq];
        qa[kk][0] = lo.x; qa[kk][1] = hi.x; qa[kk][2] = lo.y; qa[kk][3] = hi.y;
    }

    float m_lo = -1e30f, m_hi = -1e30f, l_lo = 0.f, l_hi = 0.f;
    float o[8][4];
#pragma unroll
    for (int nt = 0; nt < 8; nt++)
#pragma unroll
        for (int i = 0; i < 4; i++) o[nt][i] = 0.f;

    for (int it = 0; it < NT; it++) {
        if (it + 1 < NT) {
            issue(it + 1);
            asm volatile("cp.async.wait_group 1;");
        } else {
            asm volatile("cp.async.wait_group 0;");
        }
        __syncthreads();
        const int bf = it & 1;
        const float* Ks = Kb + bf * (64 * STR);
        const float* Vs = Vb + bf * (64 * STR);
        const float* mk = Mb + bf * 64;

        // ---- S = Q K^T ----
        float s[8][4];
#pragma unroll
        for (int nt = 0; nt < 8; nt++)
#pragma unroll
            for (int i = 0; i < 4; i++) s[nt][i] = 0.f;
#pragma unroll
        for (int kk = 0; kk < 8; kk++) {
#pragma unroll
            for (int nt = 0; nt < 8; nt++) {
                uint2 bb = *(const uint2*)&Ks[(8 * nt + g) * STR + 8 * kk + 2 * tq];
                mma8(s[nt], qa[kk][0], qa[kk][1], qa[kk][2], qa[kk][3], bb.x, bb.y);
            }
        }

        // ---- warp-local online softmax (log2 domain) ----
        const float SC2 = 0.125f * LOG2E;
        float vmx_lo = -1e30f, vmx_hi = -1e30f;
#pragma unroll
        for (int nt = 0; nt < 8; nt++) {
            float2 mm = *(const float2*)&mk[8 * nt + 2 * tq];
            s[nt][0] = s[nt][0] * SC2 + mm.x;
            s[nt][1] = s[nt][1] * SC2 + mm.y;
            s[nt][2] = s[nt][2] * SC2 + mm.x;
            s[nt][3] = s[nt][3] * SC2 + mm.y;
            vmx_lo = fmaxf(vmx_lo, fmaxf(s[nt][0], s[nt][1]));
            vmx_hi = fmaxf(vmx_hi, fmaxf(s[nt][2], s[nt][3]));
        }
        vmx_lo = fmaxf(vmx_lo, __shfl_xor_sync(0xffffffffu, vmx_lo, 1));
        vmx_lo = fmaxf(vmx_lo, __shfl_xor_sync(0xffffffffu, vmx_lo, 2));
        vmx_hi = fmaxf(vmx_hi, __shfl_xor_sync(0xffffffffu, vmx_hi, 1));
        vmx_hi = fmaxf(vmx_hi, __shfl_xor_sync(0xffffffffu, vmx_hi, 2));
        float Mlo = fmaxf(m_lo, vmx_lo), Mhi = fmaxf(m_hi, vmx_hi);
        float clo = exp2f(m_lo - Mlo), chi = exp2f(m_hi - Mhi);
        m_lo = Mlo; m_hi = Mhi;

        float slo = 0.f, shi = 0.f;
#pragma unroll
        for (int nt = 0; nt < 8; nt++) {
            float p0 = exp2f(s[nt][0] - Mlo), p1 = exp2f(s[nt][1] - Mlo);
            float p2 = exp2f(s[nt][2] - Mhi), p3 = exp2f(s[nt][3] - Mhi);
            slo += p0 + p1; shi += p2 + p3;
            s[nt][0] = __uint_as_float(f2tf(p0));
            s[nt][1] = __uint_as_float(f2tf(p1));
            s[nt][2] = __uint_as_float(f2tf(p2));
            s[nt][3] = __uint_as_float(f2tf(p3));
        }
        slo += __shfl_xor_sync(0xffffffffu, slo, 1);
        slo += __shfl_xor_sync(0xffffffffu, slo, 2);
        shi += __shfl_xor_sync(0xffffffffu, shi, 1);
        shi += __shfl_xor_sync(0xffffffffu, shi, 2);
        l_lo = l_lo * clo + slo;
        l_hi = l_hi * chi + shi;

        // ---- O = O*corr + P V ----
#pragma unroll
        for (int nt = 0; nt < 8; nt++) {
            o[nt][0] *= clo; o[nt][1] *= clo;
            o[nt][2] *= chi; o[nt][3] *= chi;
        }
#pragma unroll
        for (int kc = 0; kc < 8; kc++) {
            unsigned a0 = __float_as_uint(s[kc][0]);
            unsigned a1 = __float_as_uint(s[kc][2]);
            unsigned a2 = __float_as_uint(s[kc][1]);
            unsigned a3 = __float_as_uint(s[kc][3]);
#pragma unroll
            for (int nh = 0; nh < 8; nh++) {
                uint2 bb = *(const uint2*)&Vs[(8 * nh + g) * STR + 8 * kc + 2 * tq];
                mma8(o[nh], a0, a1, a2, a3, bb.x, bb.y);
            }
        }
        __syncthreads();
    }

    // ---- epilogue: unnormalized O + (m, l) in log2 domain ----
    size_t rlo = (size_t)z * ROWS + (size_t)b * SEQ + q0 + r0 + g;
    size_t rhi = rlo + 8;
#pragma unroll
    for (int nt = 0; nt < 8; nt++) {
        int c0 = 8 * nt + 2 * tq;
        *(float2*)&g_opart[rlo * 64 + c0] = make_float2(o[nt][0], o[nt][1]);
        *(float2*)&g_opart[rhi * 64 + c0] = make_float2(o[nt][2], o[nt][3]);
    }
    if (tq == 0) {
        g_ml[rlo * 2] = m_lo; g_ml[rlo * 2 + 1] = l_lo;
        g_ml[rhi * 2] = m_hi; g_ml[rhi * 2 + 1] = l_hi;
    }
}

// ===========================================================================
// Split-K combine (m values are log2-domain)
// ===========================================================================
__global__ void __launch_bounds__(256) combine_kernel(float* __restrict__ out) {
    int t = threadIdx.x;
    int row = blockIdx.x * 16 + (t >> 4);
    int c   = (t & 15) * 4;
    float m0 = g_ml[(size_t)row * 2], l0 = g_ml[(size_t)row * 2 + 1];
    float m1 = g_ml[((size_t)ROWS + row) * 2], l1 = g_ml[((size_t)ROWS + row) * 2 + 1];
    float mx = fmaxf(m0, m1);
    float w0 = exp2f(m0 - mx), w1 = exp2f(m1 - mx);
    float inv = 1.f / (w0 * l0 + w1 * l1);
    w0 *= inv; w1 *= inv;
    float4 a = *(const float4*)&g_opart[(size_t)row * 64 + c];
    float4 d = *(const float4*)&g_opart[((size_t)ROWS + row) * 64 + c];
    float4 r = make_float4(w0 * a.x + w1 * d.x, w0 * a.y + w1 * d.y,
                           w0 * a.z + w1 * d.z, w0 * a.w + w1 * d.w);
    *(float4*)&out[(size_t)row * 64 + c] = r;
}

// ---------------------------------------------------------------------------
extern "C" void kernel_launch(void* const* d_in, const int* in_sizes, int n_in,
                              void* d_out, int out_size) {
    const float* x    = (const float*)d_in[0];
    const float* Wq   = (const float*)d_in[1];
    const float* Wk   = (const float*)d_in[2];
    const float* Wv   = (const float*)d_in[3];
    const int*   mask = (const int*)d_in[4];
    float*       out  = (float*)d_out;

    cudaFuncSetAttribute(proj_kernel, cudaFuncAttributeMaxDynamicSharedMemorySize,
                         PROJ_SMEM_B);
    cudaFuncSetAttribute(attn_kernel, cudaFuncAttributeMaxDynamicSharedMemorySize,
                         ATTN_SMEM_B);

    wcvt_kernel<<<192, 256>>>(Wq, Wk, Wv);
    proj_kernel<<<ROWS / 64, 256, PROJ_SMEM_B>>>(x);
    attn_kernel<<<dim3(SEQ / 128, BATCH, KSPLIT), 256, ATTN_SMEM_B>>>(mask);
    combine_kernel<<<ROWS / 16, 256>>>(out);
}

// round 5
// speedup vs baseline: 4.5047x; 1.0656x over previous
#include <cuda_runtime.h>
#include <cstdint>

#define BATCH 4
#define SEQ   4096
#define EMBED 1024
#define HEAD  64
#define ROWS  (BATCH * SEQ)
#define KSPLIT 2
#define KRANGE (SEQ / KSPLIT)
#define NT     (KRANGE / 64)

#define LOG2E 1.4426950408889634f

__device__ float g_w [192 * EMBED];
__device__ float g_q [ROWS * HEAD];
__device__ float g_k [ROWS * HEAD];
__device__ float g_vt[BATCH * HEAD * SEQ];
__device__ float g_opart[KSPLIT * ROWS * HEAD];
__device__ float g_ml  [KSPLIT * ROWS * 2];

// ---------------------------------------------------------------------------
__device__ __forceinline__ unsigned f2tf(float f) {
    unsigned u;
    asm("cvt.rna.tf32.f32 %0, %1;" : "=r"(u) : "f"(f));
    return u;
}
__device__ __forceinline__ float f2tff(float f) { return __uint_as_float(f2tf(f)); }

__device__ __forceinline__ void mma8(float* d, unsigned a0, unsigned a1,
                                     unsigned a2, unsigned a3,
                                     unsigned b0, unsigned b1) {
    asm("mma.sync.aligned.m16n8k8.row.col.f32.tf32.tf32.f32 "
        "{%0,%1,%2,%3},{%4,%5,%6,%7},{%8,%9},{%0,%1,%2,%3};"
        : "+f"(d[0]), "+f"(d[1]), "+f"(d[2]), "+f"(d[3])
        : "r"(a0), "r"(a1), "r"(a2), "r"(a3), "r"(b0), "r"(b1));
}

__device__ __forceinline__ void cp16(void* sptr, const void* gaddr) {
    uint32_t sa = (uint32_t)__cvta_generic_to_shared(sptr);
    asm volatile("cp.async.ca.shared.global [%0], [%1], 16;" ::"r"(sa), "l"(gaddr));
}
__device__ __forceinline__ void cp_commit() { asm volatile("cp.async.commit_group;"); }

// ===========================================================================
// Weight pre-round: g_w[n][e] = tf32(W[n][e])
// ===========================================================================
__global__ void __launch_bounds__(256) wcvt_kernel(const float* __restrict__ Wq,
                                                   const float* __restrict__ Wk,
                                                   const float* __restrict__ Wv) {
    int idx4 = blockIdx.x * 256 + threadIdx.x;
    int n  = idx4 >> 8;
    int e4 = idx4 & 255;
    const float* src = (n < 64) ? Wq : (n < 128) ? Wk : Wv;
    float4 v = *(const float4*)(src + (size_t)(n & 63) * EMBED + 4 * e4);
    v.x = f2tff(v.x); v.y = f2tff(v.y); v.z = f2tff(v.z); v.w = f2tff(v.w);
    *(float4*)(g_w + (size_t)n * EMBED + 4 * e4) = v;
}

// ===========================================================================
// Projection (tf32 mma): tile 64 rows x 192 cols, 256 threads.
// ===========================================================================
#define PKC   32
#define PSTR  40
#define XS_F  (64 * PSTR)
#define WS_F  (192 * PSTR)
#define PROJ_SMEM_F (2 * (XS_F + WS_F))
#define PROJ_SMEM_B (PROJ_SMEM_F * 4)

__global__ void __launch_bounds__(256, 2)
proj_kernel(const float* __restrict__ x) {
    extern __shared__ float sm[];
    const int t = threadIdx.x, lane = t & 31, wid = t >> 5;
    const int g = lane >> 2, tq = lane & 3;
    const int wm = wid & 1, wn = wid >> 1;
    const size_t row0 = (size_t)blockIdx.x * 64;

    float acc[2][6][4];
#pragma unroll
    for (int mt = 0; mt < 2; mt++)
#pragma unroll
        for (int nt = 0; nt < 6; nt++)
#pragma unroll
            for (int i = 0; i < 4; i++) acc[mt][nt][i] = 0.f;

    const int NC = EMBED / PKC;

    auto issue = [&](int c) {
        int buf = c & 1;
        int k0  = c * PKC;
        float* Xs = sm + buf * (XS_F + WS_F);
        float* Ws = Xs + XS_F;
#pragma unroll
        for (int j = 0; j < 2; j++) {
            int id = t + 256 * j;
            int r = id >> 3, q = id & 7;
            cp16(&Xs[r * PSTR + 4 * q], x + (row0 + r) * EMBED + k0 + 4 * q);
        }
#pragma unroll
        for (int j = 0; j < 6; j++) {
            int id = t + 256 * j;
            int n = id >> 3, q = id & 7;
            cp16(&Ws[n * PSTR + 4 * q], g_w + (size_t)n * EMBED + k0 + 4 * q);
        }
        cp_commit();
    };

    issue(0);
    for (int c = 0; c < NC; c++) {
        if (c + 1 < NC) {
            issue(c + 1);
            asm volatile("cp.async.wait_group 1;");
        } else {
            asm volatile("cp.async.wait_group 0;");
        }
        __syncthreads();
        const float* Xs = sm + (c & 1) * (XS_F + WS_F);
        const float* Ws = Xs + XS_F;
#pragma unroll
        for (int kk = 0; kk < 4; kk++) {
            unsigned a[2][4];
#pragma unroll
            for (int mt = 0; mt < 2; mt++) {
                int r = 32 * wm + 16 * mt + g;
                float2 lo = *(const float2*)&Xs[(r    ) * PSTR + 8 * kk + 2 * tq];
                float2 hi = *(const float2*)&Xs[(r + 8) * PSTR + 8 * kk + 2 * tq];
                a[mt][0] = f2tf(lo.x); a[mt][1] = f2tf(hi.x);
                a[mt][2] = f2tf(lo.y); a[mt][3] = f2tf(hi.y);
            }
#pragma unroll
            for (int nt = 0; nt < 6; nt++) {
                uint2 bb = *(const uint2*)&Ws[(48 * wn + 8 * nt + g) * PSTR + 8 * kk + 2 * tq];
#pragma unroll
                for (int mt = 0; mt < 2; mt++)
                    mma8(acc[mt][nt], a[mt][0], a[mt][1], a[mt][2], a[mt][3],
                         bb.x, bb.y);
            }
        }
        __syncthreads();
    }

#pragma unroll
    for (int mt = 0; mt < 2; mt++) {
#pragma unroll
        for (int nt = 0; nt < 6; nt++) {
            int c0 = 48 * wn + 8 * nt + 2 * tq;
            int msel = c0 >> 6;
            int h    = c0 & 63;
            int r1 = (int)row0 + 32 * wm + 16 * mt + g;
            int r2 = r1 + 8;
            float* a = acc[mt][nt];
            float a0 = f2tff(a[0]), a1 = f2tff(a[1]);
            float a2 = f2tff(a[2]), a3 = f2tff(a[3]);
            if (msel == 0) {
                *(float2*)&g_q[(size_t)r1 * 64 + h] = make_float2(a0, a1);
                *(float2*)&g_q[(size_t)r2 * 64 + h] = make_float2(a2, a3);
            } else if (msel == 1) {
                *(float2*)&g_k[(size_t)r1 * 64 + h] = make_float2(a0, a1);
                *(float2*)&g_k[(size_t)r2 * 64 + h] = make_float2(a2, a3);
            } else {
                int b1 = r1 >> 12, n1 = r1 & 4095;
                int b2 = r2 >> 12, n2 = r2 & 4095;
                g_vt[((size_t)b1 * 64 + h    ) * SEQ + n1] = a0;
                g_vt[((size_t)b1 * 64 + h + 1) * SEQ + n1] = a1;
                g_vt[((size_t)b2 * 64 + h    ) * SEQ + n2] = a2;
                g_vt[((size_t)b2 * 64 + h + 1) * SEQ + n2] = a3;
            }
        }
    }
}

// ===========================================================================
// Flash attention, tf32 mma. BQ = 128, BK = 64, 128 threads (4 warps, each
// warp owns 32 rows x 64 cols -> every K/V fragment feeds 2 row-group MMAs).
// Q fragments in registers; warp-local softmax (log2 domain); P in registers.
// Split-K x2. 2 CTAs/SM.
// ===========================================================================
#define STR 72
#define S_Q  0                        // 128 x 72
#define S_K  9216                     // 2 x 64 x 72
#define S_V  18432                    // 2 x 64 x 72
#define S_M  27648                    // 2 x 64
#define ATTN_SMEM_F 27776
#define ATTN_SMEM_B (ATTN_SMEM_F * 4) // 111104 B

__global__ void __launch_bounds__(128, 2)
attn_kernel(const int* __restrict__ mask) {
    extern __shared__ float sm[];
    float* Qs = sm + S_Q;
    float* Kb = sm + S_K;
    float* Vb = sm + S_V;
    float* Mb = sm + S_M;

    const int t = threadIdx.x, lane = t & 31;
    const int g = lane >> 2, tq = lane & 3;
    const int r0 = (t >> 5) * 32;     // warp's 32 query rows
    const int b  = blockIdx.y, z = blockIdx.z;
    const int q0 = blockIdx.x * 128;
    const int koff = z * KRANGE;

    const float* qbase = g_q + ((size_t)b * SEQ + q0) * HEAD;
    const float* kbase = g_k + ((size_t)b * SEQ + koff) * HEAD;
    const float* vbase = g_vt + (size_t)b * HEAD * SEQ + koff;

    // ---- stage Q (128 x 64) ----
#pragma unroll
    for (int j = 0; j < 16; j++) {
        int id = t + 128 * j;
        int r = id >> 4, q = id & 15;
        cp16(&Qs[r * STR + 4 * q], qbase + (size_t)r * 64 + 4 * q);
    }
    cp_commit();

    auto issue = [&](int it) {
        int bf = it & 1;
        float* Ks = Kb + bf * (64 * STR);
        float* Vs = Vb + bf * (64 * STR);
#pragma unroll
        for (int j = 0; j < 8; j++) {
            int id = t + 128 * j;
            int r = id >> 4, q = id & 15;
            cp16(&Ks[r * STR + 4 * q], kbase + (size_t)(it * 64 + r) * 64 + 4 * q);
            cp16(&Vs[r * STR + 4 * q], vbase + (size_t)r * SEQ + it * 64 + 4 * q);
        }
        if (t < 64)
            Mb[bf * 64 + t] = (mask[b * SEQ + koff + it * 64 + t] == 0) ? -1e30f : 0.f;
        cp_commit();
    };

    issue(0);
    asm volatile("cp.async.wait_group 1;");   // Q group done
    __syncthreads();

    // ---- hoist Q fragments (2 row groups) ----
    unsigned qa[2][8][4];
#pragma unroll
    for (int rg = 0; rg < 2; rg++)
#pragma unroll
        for (int kk = 0; kk < 8; kk++) {
            uint2 lo = *(const uint2*)&Qs[(r0 + 16 * rg + g    ) * STR + 8 * kk + 2 * tq];
            uint2 hi = *(const uint2*)&Qs[(r0 + 16 * rg + g + 8) * STR + 8 * kk + 2 * tq];
            qa[rg][kk][0] = lo.x; qa[rg][kk][1] = hi.x;
            qa[rg][kk][2] = lo.y; qa[rg][kk][3] = hi.y;
        }

    float m_lo[2] = {-1e30f, -1e30f}, m_hi[2] = {-1e30f, -1e30f};
    float l_lo[2] = {0.f, 0.f},       l_hi[2] = {0.f, 0.f};
    float o[2][8][4];
#pragma unroll
    for (int rg = 0; rg < 2; rg++)
#pragma unroll
        for (int nt = 0; nt < 8; nt++)
#pragma unroll
            for (int i = 0; i < 4; i++) o[rg][nt][i] = 0.f;

    for (int it = 0; it < NT; it++) {
        if (it + 1 < NT) {
            issue(it + 1);
            asm volatile("cp.async.wait_group 1;");
        } else {
            asm volatile("cp.async.wait_group 0;");
        }
        __syncthreads();
        const int bf = it & 1;
        const float* Ks = Kb + bf * (64 * STR);
        const float* Vs = Vb + bf * (64 * STR);
        const float* mk = Mb + bf * 64;

        // ---- S = Q K^T : each B fragment feeds both row groups ----
        float s[2][8][4];
#pragma unroll
        for (int rg = 0; rg < 2; rg++)
#pragma unroll
            for (int nt = 0; nt < 8; nt++)
#pragma unroll
                for (int i = 0; i < 4; i++) s[rg][nt][i] = 0.f;
#pragma unroll
        for (int kk = 0; kk < 8; kk++) {
#pragma unroll
            for (int nt = 0; nt < 8; nt++) {
                uint2 bb = *(const uint2*)&Ks[(8 * nt + g) * STR + 8 * kk + 2 * tq];
                mma8(s[0][nt], qa[0][kk][0], qa[0][kk][1], qa[0][kk][2], qa[0][kk][3],
                     bb.x, bb.y);
                mma8(s[1][nt], qa[1][kk][0], qa[1][kk][1], qa[1][kk][2], qa[1][kk][3],
                     bb.x, bb.y);
            }
        }

        // ---- warp-local online softmax (log2 domain), per row group ----
        const float SC2 = 0.125f * LOG2E;
        float clo[2], chi[2];
#pragma unroll
        for (int rg = 0; rg < 2; rg++) {
            float vmx_lo = -1e30f, vmx_hi = -1e30f;
#pragma unroll
            for (int nt = 0; nt < 8; nt++) {
                float2 mm = *(const float2*)&mk[8 * nt + 2 * tq];
                s[rg][nt][0] = s[rg][nt][0] * SC2 + mm.x;
                s[rg][nt][1] = s[rg][nt][1] * SC2 + mm.y;
                s[rg][nt][2] = s[rg][nt][2] * SC2 + mm.x;
                s[rg][nt][3] = s[rg][nt][3] * SC2 + mm.y;
                vmx_lo = fmaxf(vmx_lo, fmaxf(s[rg][nt][0], s[rg][nt][1]));
                vmx_hi = fmaxf(vmx_hi, fmaxf(s[rg][nt][2], s[rg][nt][3]));
            }
            vmx_lo = fmaxf(vmx_lo, __shfl_xor_sync(0xffffffffu, vmx_lo, 1));
            vmx_lo = fmaxf(vmx_lo, __shfl_xor_sync(0xffffffffu, vmx_lo, 2));
            vmx_hi = fmaxf(vmx_hi, __shfl_xor_sync(0xffffffffu, vmx_hi, 1));
            vmx_hi = fmaxf(vmx_hi, __shfl_xor_sync(0xffffffffu, vmx_hi, 2));
            float Mlo = fmaxf(m_lo[rg], vmx_lo), Mhi = fmaxf(m_hi[rg], vmx_hi);
            clo[rg] = exp2f(m_lo[rg] - Mlo);
            chi[rg] = exp2f(m_hi[rg] - Mhi);
            m_lo[rg] = Mlo; m_hi[rg] = Mhi;

            float slo = 0.f, shi = 0.f;
#pragma unroll
            for (int nt = 0; nt < 8; nt++) {
                float p0 = exp2f(s[rg][nt][0] - Mlo), p1 = exp2f(s[rg][nt][1] - Mlo);
                float p2 = exp2f(s[rg][nt][2] - Mhi), p3 = exp2f(s[rg][nt][3] - Mhi);
                slo += p0 + p1; shi += p2 + p3;
                s[rg][nt][0] = __uint_as_float(f2tf(p0));
                s[rg][nt][1] = __uint_as_float(f2tf(p1));
                s[rg][nt][2] = __uint_as_float(f2tf(p2));
                s[rg][nt][3] = __uint_as_float(f2tf(p3));
            }
            slo += __shfl_xor_sync(0xffffffffu, slo, 1);
            slo += __shfl_xor_sync(0xffffffffu, slo, 2);
            shi += __shfl_xor_sync(0xffffffffu, shi, 1);
            shi += __shfl_xor_sync(0xffffffffu, shi, 2);
            l_lo[rg] = l_lo[rg] * clo[rg] + slo;
            l_hi[rg] = l_hi[rg] * chi[rg] + shi;

#pragma unroll
            for (int nt = 0; nt < 8; nt++) {
                o[rg][nt][0] *= clo[rg]; o[rg][nt][1] *= clo[rg];
                o[rg][nt][2] *= chi[rg]; o[rg][nt][3] *= chi[rg];
            }
        }

        // ---- O += P V : each V fragment feeds both row groups ----
#pragma unroll
        for (int kc = 0; kc < 8; kc++) {
#pragma unroll
            for (int nh = 0; nh < 8; nh++) {
                uint2 bb = *(const uint2*)&Vs[(8 * nh + g) * STR + 8 * kc + 2 * tq];
                mma8(o[0][nh],
                     __float_as_uint(s[0][kc][0]), __float_as_uint(s[0][kc][2]),
                     __float_as_uint(s[0][kc][1]), __float_as_uint(s[0][kc][3]),
                     bb.x, bb.y);
                mma8(o[1][nh],
                     __float_as_uint(s[1][kc][0]), __float_as_uint(s[1][kc][2]),
                     __float_as_uint(s[1][kc][1]), __float_as_uint(s[1][kc][3]),
                     bb.x, bb.y);
            }
        }
        __syncthreads();
    }

    // ---- epilogue ----
#pragma unroll
    for (int rg = 0; rg < 2; rg++) {
        size_t rlo = (size_t)z * ROWS + (size_t)b * SEQ + q0 + r0 + 16 * rg + g;
        size_t rhi = rlo + 8;
#pragma unroll
        for (int nt = 0; nt < 8; nt++) {
            int c0 = 8 * nt + 2 * tq;
            *(float2*)&g_opart[rlo * 64 + c0] = make_float2(o[rg][nt][0], o[rg][nt][1]);
            *(float2*)&g_opart[rhi * 64 + c0] = make_float2(o[rg][nt][2], o[rg][nt][3]);
        }
        if (tq == 0) {
            g_ml[rlo * 2] = m_lo[rg]; g_ml[rlo * 2 + 1] = l_lo[rg];
            g_ml[rhi * 2] = m_hi[rg]; g_ml[rhi * 2 + 1] = l_hi[rg];
        }
    }
}

// ===========================================================================
// Split-K combine (m values are log2-domain)
// ===========================================================================
__global__ void __launch_bounds__(256) combine_kernel(float* __restrict__ out) {
    int t = threadIdx.x;
    int row = blockIdx.x * 16 + (t >> 4);
    int c   = (t & 15) * 4;
    float m0 = g_ml[(size_t)row * 2], l0 = g_ml[(size_t)row * 2 + 1];
    float m1 = g_ml[((size_t)ROWS + row) * 2], l1 = g_ml[((size_t)ROWS + row) * 2 + 1];
    float mx = fmaxf(m0, m1);
    float w0 = exp2f(m0 - mx), w1 = exp2f(m1 - mx);
    float inv = 1.f / (w0 * l0 + w1 * l1);
    w0 *= inv; w1 *= inv;
    float4 a = *(const float4*)&g_opart[(size_t)row * 64 + c];
    float4 d = *(const float4*)&g_opart[((size_t)ROWS + row) * 64 + c];
    float4 r = make_float4(w0 * a.x + w1 * d.x, w0 * a.y + w1 * d.y,
                           w0 * a.z + w1 * d.z, w0 * a.w + w1 * d.w);
    *(float4*)&out[(size_t)row * 64 + c] = r;
}

// ---------------------------------------------------------------------------
extern "C" void kernel_launch(void* const* d_in, const int* in_sizes, int n_in,
                              void* d_out, int out_size) {
    const float* x    = (const float*)d_in[0];
    const float* Wq   = (const float*)d_in[1];
    const float* Wk   = (const float*)d_in[2];
    const float* Wv   = (const float*)d_in[3];
    const int*   mask = (const int*)d_in[4];
    float*       out  = (float*)d_out;

    cudaFuncSetAttribute(proj_kernel, cudaFuncAttributeMaxDynamicSharedMemorySize,
                         PROJ_SMEM_B);
    cudaFuncSetAttribute(attn_kernel, cudaFuncAttributeMaxDynamicSharedMemorySize,
                         ATTN_SMEM_B);

    wcvt_kernel<<<192, 256>>>(Wq, Wk, Wv);
    proj_kernel<<<ROWS / 64, 256, PROJ_SMEM_B>>>(x);
    attn_kernel<<<dim3(SEQ / 128, BATCH, KSPLIT), 128, ATTN_SMEM_B>>>(mask);
    combine_kernel<<<ROWS / 16, 256>>>(out);
}